// round 16
// baseline (speedup 1.0000x reference)
#include <cuda_runtime.h>
#include <cuda_fp16.h>
#include <cstdint>

// 3x3 conv (NCHW fp32, pad 1, +bias) via SINGLE-PASS fp16 mma.sync GEMM.
// R16: CTA 64px x 256oc (full N), 4 warps (32x128 tiles, 2Mx2N), 18 K=64
// stages, double-buffered smem (80KB -> 2 CTAs/SM). Crossbar bytes/HMMA
// drops below tensor cycles (78us vs 98us) -> tensor becomes the limiter.
// Prep: smem-transpose x-convert (coalesced both sides) + w-convert.

#define ABUF   8192                // 64px x 64ch fp16
#define BBUF   32768               // 256oc x 64ch fp16
#define SMEMSZ 81920               // 2*ABUF + 2*BBUF
#define NSTR   445440              // 3480*128

__device__ __align__(16) __half g_xh[14254080];   // [n][r60][w58][c128]
__device__ __align__(16) __half g_wh[294912];     // [tap][oc256][ch128]

__device__ __forceinline__ uint32_t s2u(const void* p) {
    uint32_t a;
    asm("{ .reg .u64 t; cvta.to.shared.u64 t, %1; cvt.u32.u64 %0, t; }" : "=r"(a) : "l"(p));
    return a;
}
__device__ __forceinline__ void cpa16(uint32_t d, const void* s) {
    asm volatile("cp.async.cg.shared.global [%0], [%1], 16;" :: "r"(d), "l"(s) : "memory");
}
__device__ __forceinline__ void ldm4(uint32_t* r, uint32_t a) {
    asm volatile("ldmatrix.sync.aligned.m8n8.x4.shared.b16 {%0,%1,%2,%3}, [%4];"
        : "=r"(r[0]), "=r"(r[1]), "=r"(r[2]), "=r"(r[3]) : "r"(a));
}
__device__ __forceinline__ void mmah(float* d, const uint32_t* a, uint32_t b0, uint32_t b1) {
    asm volatile("mma.sync.aligned.m16n8k16.row.col.f32.f16.f16.f32 "
        "{%0,%1,%2,%3}, {%4,%5,%6,%7}, {%8,%9}, {%0,%1,%2,%3};"
        : "+f"(d[0]), "+f"(d[1]), "+f"(d[2]), "+f"(d[3])
        : "r"(a[0]), "r"(a[1]), "r"(a[2]), "r"(a[3]), "r"(b0), "r"(b1));
}

// ---- prep: blocks <1920 transpose-convert x; blocks >=1920 convert w ----
__global__ void prep_kernel(const float* __restrict__ x, const float* __restrict__ w) {
    if (blockIdx.x < 1920) {
        __shared__ float tile[128][59];           // 59-pad: conflict-free reads
        const int n = blockIdx.x / 60;
        const int r = blockIdx.x % 60;
        const int row = r - 1;
        // load: coalesced along wq for each channel c
        for (int i = threadIdx.x; i < 128 * 58; i += 256) {
            int c = i / 58, wq = i - c * 58;
            int col = wq - 1;
            float v = 0.0f;
            if ((unsigned)row < 56u && (unsigned)col < 56u)
                v = x[(((size_t)n * 128 + c) * 56 + row) * 56 + col];
            tile[c][wq] = v;
        }
        __syncthreads();
        // store: coalesced along c (warp writes 256B contiguous)
        for (int i = threadIdx.x; i < 58 * 32; i += 256) {
            int wq = i >> 5, ck = i & 31;
            int c0 = ck * 4;
            __half h[4];
#pragma unroll
            for (int k = 0; k < 4; ++k)
                h[k] = __float2half(tile[c0 + k][wq]);
            *(uint2*)(g_xh + ((size_t)n * 3480 + r * 58 + wq) * 128 + c0) = *(uint2*)h;
        }
    } else if (threadIdx.x < 128) {
        int oc = blockIdx.x - 1920, ch = threadIdx.x;
        const float* src = w + ((size_t)oc * 128 + ch) * 9;
#pragma unroll
        for (int t = 0; t < 9; ++t)
            g_wh[((size_t)t * 256 + oc) * 128 + ch] = __float2half(src[t]);
    }
}

__global__ __launch_bounds__(128, 2)
void conv_mma_kernel(const float* __restrict__ bias, float* __restrict__ out) {
    extern __shared__ __align__(16) char smem[];
    const uint32_t SB = s2u(smem);       // A x2 (ABUF), then B x2 (BBUF)

    const int tid = threadIdx.x;
    const int p0  = blockIdx.x * 64;
    const int n   = blockIdx.y;

    // staging map: jj = 16B ch-chunk (0..7), tr = row group (0..15)
    const int jj = tid & 7;
    const int tr = tid >> 3;
    int q[4];
#pragma unroll
    for (int i = 0; i < 4; ++i) {
        int p = p0 + tr + 16 * i;
        q[i] = p + 2 * (p / 56);         // offset in 58-wide padded frame
    }

    // mma map: 4 warps = 2(M) x 2(N); warp tile 32x128
    const int wid = tid >> 5, l = tid & 31;
    const int m0 = (wid & 1) * 32;
    const int n0 = (wid >> 1) * 128;
    const int rA0 = m0 + (l & 15);
    const int ahx = rA0 & 7;
    const int ahi = l >> 4;
    const int rBb = (l & 7) + ((l >> 4) << 3);
    const int bhalf = (l >> 3) & 1;
    const int bhx = l & 7;

    float acc[2][16][4];                 // [m-tile][n8-tile][frag]
#pragma unroll
    for (int a = 0; a < 2; ++a)
#pragma unroll
        for (int b = 0; b < 16; ++b)
#pragma unroll
            for (int c = 0; c < 4; ++c) acc[a][b][c] = 0.0f;

    // stage s: tap = s>>1, ch-half = s&1 (64 ch per stage); slot = s&1
    auto stage = [&](int s) {
        const int t = s >> 1, kh = s & 1;
        const uint32_t slot = (uint32_t)(s & 1);
        const uint32_t ab = SB + slot * ABUF;
        const __half* asrc = g_xh + (size_t)n * NSTR
                           + (size_t)((t / 3) * 58 + (t % 3)) * 128 + kh * 64 + jj * 8;
#pragma unroll
        for (int i = 0; i < 4; ++i) {
            int r = tr + 16 * i;
            cpa16(ab + (uint32_t)r * 128 + (uint32_t)((jj ^ (r & 7)) << 4),
                  asrc + (size_t)q[i] * 128);
        }
        const uint32_t bb = SB + 2u * ABUF + slot * BBUF;
        const __half* bsrc = g_wh + (size_t)t * 32768 + kh * 64 + jj * 8;
#pragma unroll
        for (int i = 0; i < 16; ++i) {
            int r = tr + 16 * i;
            cpa16(bb + (uint32_t)r * 128 + (uint32_t)((jj ^ (r & 7)) << 4),
                  bsrc + (size_t)r * 128);
        }
        asm volatile("cp.async.commit_group;" ::: "memory");
    };

    stage(0);

#pragma unroll 1
    for (int s = 0; s < 18; ++s) {
        asm volatile("cp.async.wait_group 0;" ::: "memory");
        __syncthreads();
        if (s + 1 < 18) stage(s + 1);

        const uint32_t slot = (uint32_t)(s & 1);
        const uint32_t ab = SB + slot * ABUF;
        const uint32_t bb = SB + 2u * ABUF + slot * BBUF;
#pragma unroll
        for (int kk = 0; kk < 4; ++kk) {
            uint32_t af[2][4];
            const uint32_t ac = (uint32_t)(((kk * 2 + ahi) ^ ahx) << 4);
            ldm4(af[0], ab + (uint32_t)rA0 * 128 + ac);
            ldm4(af[1], ab + (uint32_t)rA0 * 128 + 2048 + ac);
            const uint32_t bc = (uint32_t)(((kk * 2 + bhalf) ^ bhx) << 4);
#pragma unroll
            for (int np = 0; np < 8; ++np) {
                uint32_t bf[4];
                ldm4(bf, bb + (uint32_t)(n0 + np * 16 + rBb) * 128 + bc);
                mmah(acc[0][2 * np],     af[0], bf[0], bf[1]);
                mmah(acc[0][2 * np + 1], af[0], bf[2], bf[3]);
                mmah(acc[1][2 * np],     af[1], bf[0], bf[1]);
                mmah(acc[1][2 * np + 1], af[1], bf[2], bf[3]);
            }
        }
    }

    // ---- epilogue: +bias, stores (exact cover) ----
    const int rbase = p0 + m0 + (l >> 2);
    const int cb = n0 + (l & 3) * 2;
#pragma unroll
    for (int mt = 0; mt < 2; ++mt)
#pragma unroll
        for (int h2 = 0; h2 < 2; ++h2) {
            const int p = rbase + mt * 16 + h2 * 8;
#pragma unroll
            for (int nt = 0; nt < 16; ++nt) {
                const int oc = cb + nt * 8;
                float* op = out + ((size_t)n * 256 + oc) * 3136 + p;
                op[0]    = acc[mt][nt][h2 * 2]     + __ldg(&bias[oc]);
                op[3136] = acc[mt][nt][h2 * 2 + 1] + __ldg(&bias[oc + 1]);
            }
        }
}

extern "C" void kernel_launch(void* const* d_in, const int* in_sizes, int n_in,
                              void* d_out, int out_size)
{
    const float* x    = (const float*)d_in[0];
    const float* w    = (const float*)d_in[1];
    const float* bias = (const float*)d_in[2];
    float* out        = (float*)d_out;

    cudaFuncSetAttribute(conv_mma_kernel,
                         cudaFuncAttributeMaxDynamicSharedMemorySize, SMEMSZ);

    prep_kernel<<<2176, 256>>>(x, w);   // 1920 x-blocks + 256 w-blocks
    dim3 grid(49, 32, 1);               // 49 px-blocks of 64, 32 images
    conv_mma_kernel<<<grid, 128, SMEMSZ>>>(bias, out);
}

// round 17
// speedup vs baseline: 1.1112x; 1.1112x over previous
#include <cuda_runtime.h>
#include <cuda_fp16.h>
#include <cstdint>

// 3x3 conv (NCHW fp32, pad 1, +bias) via SINGLE-PASS fp16 mma.sync GEMM.
// R17: R13 config (64px x 128oc, 4 warps 32x64, 18 K=64 stages, 48KB smem)
// squeezed to 4 CTAs/SM via __launch_bounds__(128,4): 16 warps/SM covers
// LDSM/barrier stalls; waves 8 -> 6. Reg budget audit: 64 acc + ~46 misc.

#define ABUF   8192                // 64px x 64ch fp16
#define BBUF   16384               // 128oc x 64ch fp16
#define SMEMSZ 49152               // 2*ABUF + 2*BBUF
#define NSTR   445440              // 3480*128

__device__ __align__(16) __half g_xh[14254080];   // [n][r60][w58][c128]
__device__ __align__(16) __half g_wh[294912];     // [ob*9+tap][oc128][ch128]

__device__ __forceinline__ uint32_t s2u(const void* p) {
    uint32_t a;
    asm("{ .reg .u64 t; cvta.to.shared.u64 t, %1; cvt.u32.u64 %0, t; }" : "=r"(a) : "l"(p));
    return a;
}
__device__ __forceinline__ void cpa16(uint32_t d, const void* s) {
    asm volatile("cp.async.cg.shared.global [%0], [%1], 16;" :: "r"(d), "l"(s) : "memory");
}
__device__ __forceinline__ void ldm4(uint32_t* r, uint32_t a) {
    asm volatile("ldmatrix.sync.aligned.m8n8.x4.shared.b16 {%0,%1,%2,%3}, [%4];"
        : "=r"(r[0]), "=r"(r[1]), "=r"(r[2]), "=r"(r[3]) : "r"(a));
}
__device__ __forceinline__ void mmah(float* d, const uint32_t* a, uint32_t b0, uint32_t b1) {
    asm volatile("mma.sync.aligned.m16n8k16.row.col.f32.f16.f16.f32 "
        "{%0,%1,%2,%3}, {%4,%5,%6,%7}, {%8,%9}, {%0,%1,%2,%3};"
        : "+f"(d[0]), "+f"(d[1]), "+f"(d[2]), "+f"(d[3])
        : "r"(a[0]), "r"(a[1]), "r"(a[2]), "r"(a[3]), "r"(b0), "r"(b1));
}

// ---- merged prep: blocks <3480 convert x (NHWC+halo); else convert w ----
__global__ void prep_kernel(const float* __restrict__ x, const float* __restrict__ w) {
    if (blockIdx.x < 3480) {
        int i = blockIdx.x * 256 + threadIdx.x;       // < 890880
        int wq = i % 58;  i /= 58;
        int r  = i % 60;  i /= 60;
        int c16 = i & 7;
        int n   = i >> 3;
        const int row = r - 1, col = wq - 1;
        const bool v = (unsigned)row < 56u && (unsigned)col < 56u;
        const float* src = x + (((size_t)n * 128 + c16 * 16) * 56 + row) * 56 + col;
        __half hb[16];
#pragma unroll
        for (int j = 0; j < 16; ++j)
            hb[j] = __float2half(v ? __ldg(src + (size_t)j * 3136) : 0.0f);
        size_t base = ((size_t)n * 3480 + r * 58 + wq) * 128 + c16 * 16;
        *(uint4*)(g_xh + base)     = *(uint4*)hb;
        *(uint4*)(g_xh + base + 8) = *(uint4*)(hb + 8);
    } else if (threadIdx.x < 128) {
        int oc = blockIdx.x - 3480, ch = threadIdx.x;
        int ob = oc >> 7, ocb = oc & 127;
        const float* src = w + ((size_t)oc * 128 + ch) * 9;
#pragma unroll
        for (int t = 0; t < 9; ++t)
            g_wh[((size_t)(ob * 9 + t) * 128 + ocb) * 128 + ch] = __float2half(src[t]);
    }
}

__global__ __launch_bounds__(128, 4)
void conv_mma_kernel(const float* __restrict__ bias, float* __restrict__ out) {
    extern __shared__ __align__(16) char smem[];
    const uint32_t SB = s2u(smem);       // A x2 (ABUF), then B x2 (BBUF)

    const int tid = threadIdx.x;
    const int p0  = blockIdx.x * 64;
    const int ob  = blockIdx.y;
    const int n   = blockIdx.z;

    // staging map: jj = 16B ch-chunk (0..7), tr = row group (0..15)
    const int jj = tid & 7;
    const int tr = tid >> 3;
    int q[4];
#pragma unroll
    for (int i = 0; i < 4; ++i) {
        int p = p0 + tr + 16 * i;
        q[i] = p + 2 * (p / 56);         // offset in 58-wide padded frame
    }

    // mma map: 4 warps = 2(M) x 2(N); warp tile 32x64
    const int wid = tid >> 5, l = tid & 31;
    const int m0 = (wid & 1) * 32;
    const int n0 = (wid >> 1) * 64;
    const int rA0 = m0 + (l & 15);
    const int ahx = rA0 & 7;
    const int ahi = l >> 4;
    const int rBb = (l & 7) + ((l >> 4) << 3);
    const int bhalf = (l >> 3) & 1;
    const int bhx = l & 7;

    float acc[2][8][4];                  // [m-tile][n8-tile][frag]
#pragma unroll
    for (int a = 0; a < 2; ++a)
#pragma unroll
        for (int b = 0; b < 8; ++b)
#pragma unroll
            for (int c = 0; c < 4; ++c) acc[a][b][c] = 0.0f;

    // stage s: tap = s>>1, ch-half = s&1 (64 ch per stage); slot = s&1
    auto stage = [&](int s) {
        const int t = s >> 1, kh = s & 1;
        const uint32_t slot = (uint32_t)(s & 1);
        const uint32_t ab = SB + slot * ABUF;
        const __half* asrc = g_xh + (size_t)n * NSTR
                           + (size_t)((t / 3) * 58 + (t % 3)) * 128 + kh * 64 + jj * 8;
#pragma unroll
        for (int i = 0; i < 4; ++i) {
            int r = tr + 16 * i;
            cpa16(ab + (uint32_t)r * 128 + (uint32_t)((jj ^ (r & 7)) << 4),
                  asrc + (size_t)q[i] * 128);
        }
        const uint32_t bb = SB + 2u * ABUF + slot * BBUF;
        const __half* bsrc = g_wh + (size_t)(ob * 9 + t) * 16384 + kh * 64 + jj * 8;
#pragma unroll
        for (int i = 0; i < 8; ++i) {
            int r = tr + 16 * i;
            cpa16(bb + (uint32_t)r * 128 + (uint32_t)((jj ^ (r & 7)) << 4),
                  bsrc + (size_t)r * 128);
        }
        asm volatile("cp.async.commit_group;" ::: "memory");
    };

    stage(0);

#pragma unroll 1
    for (int s = 0; s < 18; ++s) {
        asm volatile("cp.async.wait_group 0;" ::: "memory");
        __syncthreads();
        if (s + 1 < 18) stage(s + 1);

        const uint32_t slot = (uint32_t)(s & 1);
        const uint32_t ab = SB + slot * ABUF;
        const uint32_t bb = SB + 2u * ABUF + slot * BBUF;
#pragma unroll
        for (int kk = 0; kk < 4; ++kk) {
            uint32_t af[2][4];
            const uint32_t ac = (uint32_t)(((kk * 2 + ahi) ^ ahx) << 4);
            ldm4(af[0], ab + (uint32_t)rA0 * 128 + ac);
            ldm4(af[1], ab + (uint32_t)rA0 * 128 + 2048 + ac);
            const uint32_t bc = (uint32_t)(((kk * 2 + bhalf) ^ bhx) << 4);
#pragma unroll
            for (int np = 0; np < 4; ++np) {
                uint32_t bf[4];
                ldm4(bf, bb + (uint32_t)(n0 + np * 16 + rBb) * 128 + bc);
                mmah(acc[0][2 * np],     af[0], bf[0], bf[1]);
                mmah(acc[0][2 * np + 1], af[0], bf[2], bf[3]);
                mmah(acc[1][2 * np],     af[1], bf[0], bf[1]);
                mmah(acc[1][2 * np + 1], af[1], bf[2], bf[3]);
            }
        }
    }

    // ---- epilogue: +bias, stores (exact cover) ----
    const int rbase = p0 + m0 + (l >> 2);
    const int cb = n0 + (l & 3) * 2;
#pragma unroll
    for (int mt = 0; mt < 2; ++mt)
#pragma unroll
        for (int h2 = 0; h2 < 2; ++h2) {
            const int p = rbase + mt * 16 + h2 * 8;
#pragma unroll
            for (int nt = 0; nt < 8; ++nt) {
                const int oc = ob * 128 + cb + nt * 8;
                float* op = out + ((size_t)n * 256 + oc) * 3136 + p;
                op[0]    = acc[mt][nt][h2 * 2]     + __ldg(&bias[oc]);
                op[3136] = acc[mt][nt][h2 * 2 + 1] + __ldg(&bias[oc + 1]);
            }
        }
}

extern "C" void kernel_launch(void* const* d_in, const int* in_sizes, int n_in,
                              void* d_out, int out_size)
{
    const float* x    = (const float*)d_in[0];
    const float* w    = (const float*)d_in[1];
    const float* bias = (const float*)d_in[2];
    float* out        = (float*)d_out;

    cudaFuncSetAttribute(conv_mma_kernel,
                         cudaFuncAttributeMaxDynamicSharedMemorySize, SMEMSZ);

    prep_kernel<<<3736, 256>>>(x, w);
    dim3 grid(49, 2, 32);
    conv_mma_kernel<<<grid, 128, SMEMSZ>>>(bias, out);
}